// round 14
// baseline (speedup 1.0000x reference)
#include <cuda_runtime.h>

#define N_NODES 100000
#define N_EDGES 1600000
#define F 48
#define FG (F / 4)            // 12 float4 groups per feature row
#define CAP 64                // bucket capacity per node (deg ~ Poisson(16))

// Scratch (static device arrays; no allocation allowed)
__device__ int   g_cursor[N_NODES];              // doubles as degree after fill
__device__ float g_dinv[N_NODES];
__device__ int   g_col[N_NODES * CAP];           // bucketed CSR columns
// xs2: per node a 256B slot = two 128B-aligned half-rows of 96B each
//   bytes [0,96)    = dinv[c]*x[c], groups 0..5
//   bytes [128,224) = dinv[c]*x[c], groups 6..11
// slot N_NODES is all zeros (dummy target for tail edges).
__device__ float g_xs2[(N_NODES + 1) * 64];
__device__ float g_agg[N_NODES * F];             // normalized aggregate

// ---------------------------------------------------------------------------
// 1) zero cursors
// ---------------------------------------------------------------------------
__global__ void zero_kernel() {
    int i = blockIdx.x * blockDim.x + threadIdx.x;
    int4* c4 = reinterpret_cast<int4*>(g_cursor);
    if (i < N_NODES / 4) c4[i] = make_int4(0, 0, 0, 0);
}

// ---------------------------------------------------------------------------
// 2) bucket fill, 4 edges per thread via int4 loads
// ---------------------------------------------------------------------------
__global__ void fill_kernel(const int* __restrict__ ei) {
    int t = blockIdx.x * blockDim.x + threadIdx.x;
    if (t < N_EDGES / 4) {
        int4 r4 = __ldg(reinterpret_cast<const int4*>(ei) + t);
        int4 c4 = __ldg(reinterpret_cast<const int4*>(ei + N_EDGES) + t);
        int s0 = atomicAdd(&g_cursor[r4.x], 1);
        int s1 = atomicAdd(&g_cursor[r4.y], 1);
        int s2 = atomicAdd(&g_cursor[r4.z], 1);
        int s3 = atomicAdd(&g_cursor[r4.w], 1);
        if (s0 < CAP) g_col[r4.x * CAP + s0] = c4.x;
        if (s1 < CAP) g_col[r4.y * CAP + s1] = c4.y;
        if (s2 < CAP) g_col[r4.z * CAP + s2] = c4.z;
        if (s3 < CAP) g_col[r4.w * CAP + s3] = c4.w;
    }
}

// ---------------------------------------------------------------------------
// 3) dinv + pre-scaled features into the split-slot layout; zero dummy slot.
// ---------------------------------------------------------------------------
__global__ void scale_kernel(const float* __restrict__ x) {
    int t = blockIdx.x * blockDim.x + threadIdx.x;
    if (t < (N_NODES + 1) * FG) {
        int n = t / FG;
        int g = t % FG;
        float4 v = make_float4(0.f, 0.f, 0.f, 0.f);
        if (n < N_NODES) {
            int d = __ldg(&g_cursor[n]);
            float di = (d > 0) ? rsqrtf((float)d) : 0.0f;
            if (g == 0) g_dinv[n] = di;
            v = __ldg(reinterpret_cast<const float4*>(x) + n * FG + g);
            v.x *= di; v.y *= di; v.z *= di; v.w *= di;
        }
        int slot4 = (g < 6) ? g : (8 + (g - 6));    // float4 index inside slot
        reinterpret_cast<float4*>(g_xs2)[n * 16 + slot4] = v;
    }
}

// ---------------------------------------------------------------------------
// 4) gather: ONE WARP PER NODE (zero divergence, warps retire independently).
//    lane = oct*8+sub; oct = (edge-of-pair e, plane p); 8 edges/iter; tail
//    edges hit the zero dummy slot.  Octet pairs combined via shfl.xor(16).
//    (Measured 36.2us in R9.)
// ---------------------------------------------------------------------------
__global__ __launch_bounds__(512)
void gather_kernel() {
    int n = (blockIdx.x * 512 + threadIdx.x) >> 5;   // warp id == node
    if (n >= N_NODES) return;
    int lane = threadIdx.x & 31;
    int oct = lane >> 3;
    int sub = lane & 7;
    int e = oct >> 1;                  // which edge of the pair
    int p = oct & 1;                   // which 96B half-row
    unsigned sof = (unsigned)(p * 128) + (sub < 6 ? (unsigned)(sub * 16) : 0u);

    int deg = min(g_cursor[n], CAP);
    const int* bucket = &g_col[n * CAP];
    const char* xb = reinterpret_cast<const char*>(g_xs2);

    float4 acc = make_float4(0.f, 0.f, 0.f, 0.f);
    for (int j0 = 0; j0 < deg; j0 += 8) {
        int i0 = j0 + 0 + e, i1 = j0 + 2 + e, i2 = j0 + 4 + e, i3 = j0 + 6 + e;
        int c0 = (i0 < deg) ? __ldg(&bucket[i0]) : N_NODES;
        int c1 = (i1 < deg) ? __ldg(&bucket[i1]) : N_NODES;
        int c2 = (i2 < deg) ? __ldg(&bucket[i2]) : N_NODES;
        int c3 = (i3 < deg) ? __ldg(&bucket[i3]) : N_NODES;
        float4 v0 = __ldg(reinterpret_cast<const float4*>(xb + (unsigned)c0 * 256u + sof));
        float4 v1 = __ldg(reinterpret_cast<const float4*>(xb + (unsigned)c1 * 256u + sof));
        float4 v2 = __ldg(reinterpret_cast<const float4*>(xb + (unsigned)c2 * 256u + sof));
        float4 v3 = __ldg(reinterpret_cast<const float4*>(xb + (unsigned)c3 * 256u + sof));
        acc.x += (v0.x + v1.x) + (v2.x + v3.x);
        acc.y += (v0.y + v1.y) + (v2.y + v3.y);
        acc.z += (v0.z + v1.z) + (v2.z + v3.z);
        acc.w += (v0.w + v1.w) + (v2.w + v3.w);
    }

    acc.x += __shfl_xor_sync(0xffffffffu, acc.x, 16);
    acc.y += __shfl_xor_sync(0xffffffffu, acc.y, 16);
    acc.z += __shfl_xor_sync(0xffffffffu, acc.z, 16);
    acc.w += __shfl_xor_sync(0xffffffffu, acc.w, 16);

    if (lane < 16 && sub < 6) {
        float di = __ldg(&g_dinv[n]);
        int g = p * 6 + sub;
        float4 r = make_float4(acc.x * di, acc.y * di, acc.z * di, acc.w * di);
        *reinterpret_cast<float4*>(&g_agg[n * F + g * 4]) = r;
    }
}

// ---------------------------------------------------------------------------
// 5) linear + bias + relu.  Block = 384 threads, 64 nodes, 8 outputs/thread.
//    agg tile staged to smem as float4 (2 LDG.128/thread); FMA loop reads
//    agg via LDS.128 (12 per node per thread) and Wt via broadcast LDS.
// ---------------------------------------------------------------------------
#define LNPB 64
__global__ __launch_bounds__(384)
void linear_kernel(const float* __restrict__ W,
                   const float* __restrict__ b,
                   float* __restrict__ out) {
    __shared__ float Wt[F * F];                 // Wt[k*F + of] = W[of*F + k]
    __shared__ float agg_s[LNPB * F];

    int tid = threadIdx.x;
    for (int i = tid; i < F * F; i += 384) {
        int of = i / F, k = i % F;
        Wt[k * F + of] = __ldg(&W[i]);
    }

    int node0 = blockIdx.x * LNPB;
    {
        const float4* src = reinterpret_cast<const float4*>(g_agg);
        float4* dst = reinterpret_cast<float4*>(agg_s);
        int base = node0 * FG;
        #pragma unroll
        for (int r = 0; r < 2; r++) {
            int i = tid + r * 384;
            int gi = base + i;
            dst[i] = (gi < N_NODES * FG) ? src[gi]
                                         : make_float4(0.f, 0.f, 0.f, 0.f);
        }
    }
    __syncthreads();

    int of  = tid % F;             // 0..47
    int nlb = tid / F;             // 0..7
    const float4* agg4 = reinterpret_cast<const float4*>(agg_s);
    float bias = __ldg(&b[of]);
    float a0 = bias, a1 = bias, a2 = bias, a3 = bias;
    float a4 = bias, a5 = bias, a6 = bias, a7 = bias;
    #pragma unroll
    for (int k4 = 0; k4 < FG; k4++) {
        int kb = k4 * 4;
        float w0 = Wt[(kb + 0) * F + of];
        float w1 = Wt[(kb + 1) * F + of];
        float w2 = Wt[(kb + 2) * F + of];
        float w3 = Wt[(kb + 3) * F + of];
        #define DO_NODE(m, am)                                           \
        {                                                                \
            float4 av = agg4[(nlb + 8 * m) * FG + k4];                   \
            am = fmaf(av.x, w0, am); am = fmaf(av.y, w1, am);            \
            am = fmaf(av.z, w2, am); am = fmaf(av.w, w3, am);            \
        }
        DO_NODE(0, a0) DO_NODE(1, a1) DO_NODE(2, a2) DO_NODE(3, a3)
        DO_NODE(4, a4) DO_NODE(5, a5) DO_NODE(6, a6) DO_NODE(7, a7)
        #undef DO_NODE
    }
    int n0 = node0 + nlb;
    if (n0 +  0 < N_NODES) out[(size_t)(n0 +  0) * F + of] = fmaxf(a0, 0.f);
    if (n0 +  8 < N_NODES) out[(size_t)(n0 +  8) * F + of] = fmaxf(a1, 0.f);
    if (n0 + 16 < N_NODES) out[(size_t)(n0 + 16) * F + of] = fmaxf(a2, 0.f);
    if (n0 + 24 < N_NODES) out[(size_t)(n0 + 24) * F + of] = fmaxf(a3, 0.f);
    if (n0 + 32 < N_NODES) out[(size_t)(n0 + 32) * F + of] = fmaxf(a4, 0.f);
    if (n0 + 40 < N_NODES) out[(size_t)(n0 + 40) * F + of] = fmaxf(a5, 0.f);
    if (n0 + 48 < N_NODES) out[(size_t)(n0 + 48) * F + of] = fmaxf(a6, 0.f);
    if (n0 + 56 < N_NODES) out[(size_t)(n0 + 56) * F + of] = fmaxf(a7, 0.f);
}

// ---------------------------------------------------------------------------
extern "C" void kernel_launch(void* const* d_in, const int* in_sizes, int n_in,
                              void* d_out, int out_size) {
    const float* x  = (const float*)d_in[0];   // [N_NODES, F]
    const int*   ei = (const int*)d_in[1];     // [2, N_EDGES]
    const float* W  = (const float*)d_in[2];   // [F, F]
    const float* b  = (const float*)d_in[3];   // [F]
    float* out = (float*)d_out;

    zero_kernel<<<(N_NODES / 4 + 255) / 256, 256>>>();
    fill_kernel<<<(N_EDGES / 4 + 255) / 256, 256>>>(ei);
    scale_kernel<<<((N_NODES + 1) * FG + 255) / 256, 256>>>(x);
    gather_kernel<<<(N_NODES * 32 + 511) / 512, 512>>>();
    linear_kernel<<<(N_NODES + LNPB - 1) / LNPB, 384>>>(W, b, out);
}